// round 7
// baseline (speedup 1.0000x reference)
#include <cuda_runtime.h>
#include <cuda_fp16.h>
#include <math.h>

#define NMAX 50048
#define EMAX 1700000
#define NBLK ((NMAX + 1023) / 1024)

// ---------------- scratch (device globals) ----------------------------------
__device__ __half g_tb[(size_t)NMAX * 128];  // x@W1 (fp16 gather table)
__device__ __half g_hb[(size_t)NMAX * 128];  // hidden after relu (fp16 table)
__device__ __half g_zh[(size_t)NMAX * 64];   // z (fp16 gather table)
__device__ float g_acc[(size_t)NMAX * 128];  // aggregated h (fp32)
__device__ float g_az[(size_t)NMAX * 64];    // aggregated z
__device__ float g_dinv[NMAX];               // deg^-0.5
__device__ int   g_cnt[NMAX];                // in-degree (real edges)
__device__ int   g_off[NMAX];                // CSR row offsets
__device__ int   g_rank[EMAX];               // per-edge rank within dst bucket
__device__ int   g_bsum[NBLK];               // scan block sums
__device__ uint2 g_edge[EMAX];               // CSR (src, weight-bits)
__device__ __half g_w1h[128 * 128];          // W1 fp16
__device__ __half g_wdxh[64 * 128];          // Wdx fp16
__device__ __half g_wph[128 * 128];          // [Wmu|Wls] fp16 hi
__device__ __half g_wpl[128 * 128];          // [Wmu|Wls] fp16 lo (residual)
__device__ float g_bpack[128];               // [bmu | bls]

// ---------------- weight conversion (independent branch) ---------------------
__global__ void cvt_weights(const float* __restrict__ W1, const float* __restrict__ Wdx,
                            const float* __restrict__ Wmu, const float* __restrict__ Wls,
                            const float* __restrict__ bmu, const float* __restrict__ bls)
{
    int i = blockIdx.x * blockDim.x + threadIdx.x;
    if (i < 128 * 128) g_w1h[i] = __float2half_rn(W1[i]);
    if (i < 64 * 128) g_wdxh[i] = __float2half_rn(Wdx[i]);
    if (i < 128 * 128) {
        int row = i >> 7, col = i & 127;
        float v = (col < 64) ? Wmu[row * 64 + col] : Wls[row * 64 + (col - 64)];
        __half h = __float2half_rn(v);
        g_wph[i] = h;
        g_wpl[i] = __float2half_rn(v - __half2float(h));
    }
    if (i < 64) { g_bpack[i] = bmu[i]; g_bpack[64 + i] = bls[i]; }
}

// ---------------- degree / CSR build ----------------------------------------
__global__ void zero_cnt(int n) {
    int i = blockIdx.x * blockDim.x + threadIdx.x;
    if (i < n) g_cnt[i] = 0;
}
// 4 edges per thread; records per-edge rank (atomicAdd return)
__global__ void cnt_count4(const int* __restrict__ dst, int e) {
    int base = (blockIdx.x * blockDim.x + threadIdx.x) * 4;
    if (base + 4 <= e) {
        int4 d = *reinterpret_cast<const int4*>(dst + base);
        int r0 = atomicAdd(&g_cnt[d.x], 1);
        int r1 = atomicAdd(&g_cnt[d.y], 1);
        int r2 = atomicAdd(&g_cnt[d.z], 1);
        int r3 = atomicAdd(&g_cnt[d.w], 1);
        *reinterpret_cast<int4*>(g_rank + base) = make_int4(r0, r1, r2, r3);
    } else {
        for (int i = base; i < e; i++)
            g_rank[i] = atomicAdd(&g_cnt[dst[i]], 1);
    }
}
// block scan + dinv in one pass
__global__ __launch_bounds__(1024) void scan_blocks(int n) {
    __shared__ int sh[1024];
    int tid = threadIdx.x;
    int i = blockIdx.x * 1024 + tid;
    int v = (i < n) ? g_cnt[i] : 0;
    if (i < n) g_dinv[i] = rsqrtf(1.0f + (float)v);
    sh[tid] = v;
    __syncthreads();
#pragma unroll
    for (int off = 1; off < 1024; off <<= 1) {
        int t = (tid >= off) ? sh[tid - off] : 0;
        __syncthreads();
        sh[tid] += t;
        __syncthreads();
    }
    if (i < n) g_off[i] = sh[tid] - v;
    if (tid == 1023) g_bsum[blockIdx.x] = sh[1023];
}
// every block redundantly scans the <=64 block sums, then adds to its range
__global__ __launch_bounds__(256) void add_bsum2(int n, int nb) {
    __shared__ int sh[64];
    int tid = threadIdx.x;
    if (tid < 64) sh[tid] = (tid < nb) ? g_bsum[tid] : 0;
    __syncthreads();
#pragma unroll
    for (int off = 1; off < 64; off <<= 1) {
        int t = (tid < 64 && tid >= off) ? sh[tid - off] : 0;
        __syncthreads();
        if (tid < 64) sh[tid] += t;
        __syncthreads();
    }
    int i = blockIdx.x * blockDim.x + tid;
    if (i < n) {
        int b = i >> 10;
        g_off[i] += (b == 0) ? 0 : sh[b - 1];
    }
}
// atomic-free fill: pos = off[dst] + rank; 4 edges/thread
__global__ void csr_fill4(const int* __restrict__ src, const int* __restrict__ dst, int e) {
    int base = (blockIdx.x * blockDim.x + threadIdx.x) * 4;
    if (base + 4 <= e) {
        int4 s = *reinterpret_cast<const int4*>(src + base);
        int4 d = *reinterpret_cast<const int4*>(dst + base);
        int4 r = *reinterpret_cast<const int4*>(g_rank + base);
        float ds0 = g_dinv[s.x], ds1 = g_dinv[s.y], ds2 = g_dinv[s.z], ds3 = g_dinv[s.w];
        float dd0 = g_dinv[d.x], dd1 = g_dinv[d.y], dd2 = g_dinv[d.z], dd3 = g_dinv[d.w];
        g_edge[g_off[d.x] + r.x] = make_uint2((unsigned)s.x, __float_as_uint(ds0 * dd0));
        g_edge[g_off[d.y] + r.y] = make_uint2((unsigned)s.y, __float_as_uint(ds1 * dd1));
        g_edge[g_off[d.z] + r.z] = make_uint2((unsigned)s.z, __float_as_uint(ds2 * dd2));
        g_edge[g_off[d.w] + r.w] = make_uint2((unsigned)s.w, __float_as_uint(ds3 * dd3));
    } else {
        for (int i = base; i < e; i++) {
            int s = src[i], d = dst[i];
            g_edge[g_off[d] + g_rank[i]] =
                make_uint2((unsigned)s, __float_as_uint(g_dinv[s] * g_dinv[d]));
        }
    }
}

// ---------------- fp16 gather helpers ----------------------------------------
__device__ __forceinline__ void acc_h4(float4& acc, uint2 q, float w) {
    __half2 p0 = *reinterpret_cast<__half2*>(&q.x);
    __half2 p1 = *reinterpret_cast<__half2*>(&q.y);
    float2 f0 = __half22float2(p0);
    float2 f1 = __half22float2(p1);
    acc.x += w * f0.x; acc.y += w * f0.y;
    acc.z += w * f1.x; acc.w += w * f1.y;
}
__device__ __forceinline__ void acc_h2(float2& acc, unsigned q, float w) {
    __half2 p = *reinterpret_cast<__half2*>(&q);
    float2 f = __half22float2(p);
    acc.x += w * f.x; acc.y += w * f.y;
}

// ---------------- aggregation: warp per node, 128-wide, fp16 table -----------
__global__ __launch_bounds__(256) void agg128h(
    const __half* __restrict__ feat, __half* __restrict__ outh,
    float* __restrict__ outf, const float* __restrict__ bias, int doRelu, int n)
{
    int node = (blockIdx.x * blockDim.x + threadIdx.x) >> 5;
    if (node >= n) return;
    int lane = threadIdx.x & 31;
    const uint2* fb = reinterpret_cast<const uint2*>(feat);

    float di = g_dinv[node];
    float4 acc = make_float4(0.f, 0.f, 0.f, 0.f);
    acc_h4(acc, __ldg(fb + (size_t)node * 32 + lane), di * di);

    int j = g_off[node];
    int jend = j + g_cnt[node];
    for (; j + 8 <= jend; j += 8) {
        uint2 e[8], q[8];
#pragma unroll
        for (int k = 0; k < 8; k++) e[k] = g_edge[j + k];
#pragma unroll
        for (int k = 0; k < 8; k++) q[k] = __ldg(fb + (size_t)e[k].x * 32 + lane);
#pragma unroll
        for (int k = 0; k < 8; k++) acc_h4(acc, q[k], __uint_as_float(e[k].y));
    }
    for (; j + 2 <= jend; j += 2) {
        uint2 e0 = g_edge[j], e1 = g_edge[j + 1];
        uint2 q0 = __ldg(fb + (size_t)e0.x * 32 + lane);
        uint2 q1 = __ldg(fb + (size_t)e1.x * 32 + lane);
        acc_h4(acc, q0, __uint_as_float(e0.y));
        acc_h4(acc, q1, __uint_as_float(e1.y));
    }
    for (; j < jend; j++) {
        uint2 e = g_edge[j];
        acc_h4(acc, __ldg(fb + (size_t)e.x * 32 + lane), __uint_as_float(e.y));
    }
    if (bias) {
        float4 b = __ldg(reinterpret_cast<const float4*>(bias) + lane);
        acc.x += b.x; acc.y += b.y; acc.z += b.z; acc.w += b.w;
    }
    if (doRelu) {
        acc.x = fmaxf(acc.x, 0.f); acc.y = fmaxf(acc.y, 0.f);
        acc.z = fmaxf(acc.z, 0.f); acc.w = fmaxf(acc.w, 0.f);
    }
    if (outh) {
        __half2 h0 = __floats2half2_rn(acc.x, acc.y);
        __half2 h1 = __floats2half2_rn(acc.z, acc.w);
        uint2 q;
        q.x = *reinterpret_cast<unsigned*>(&h0);
        q.y = *reinterpret_cast<unsigned*>(&h1);
        *(reinterpret_cast<uint2*>(outh) + (size_t)node * 32 + lane) = q;
    }
    if (outf) {
        *(reinterpret_cast<float4*>(outf + (size_t)node * 128) + lane) = acc;
    }
}

// ---------------- aggregation: warp per node, 64-wide, fp16 table ------------
__global__ __launch_bounds__(256) void agg64h(
    const __half* __restrict__ feat, float* __restrict__ out, int n)
{
    int node = (blockIdx.x * blockDim.x + threadIdx.x) >> 5;
    if (node >= n) return;
    int lane = threadIdx.x & 31;
    const unsigned* fb = reinterpret_cast<const unsigned*>(feat);

    float di = g_dinv[node];
    float2 acc = make_float2(0.f, 0.f);
    acc_h2(acc, __ldg(fb + (size_t)node * 32 + lane), di * di);

    int j = g_off[node];
    int jend = j + g_cnt[node];
    for (; j + 8 <= jend; j += 8) {
        uint2 e[8];
        unsigned q[8];
#pragma unroll
        for (int k = 0; k < 8; k++) e[k] = g_edge[j + k];
#pragma unroll
        for (int k = 0; k < 8; k++) q[k] = __ldg(fb + (size_t)e[k].x * 32 + lane);
#pragma unroll
        for (int k = 0; k < 8; k++) acc_h2(acc, q[k], __uint_as_float(e[k].y));
    }
    for (; j < jend; j++) {
        uint2 e = g_edge[j];
        acc_h2(acc, __ldg(fb + (size_t)e.x * 32 + lane), __uint_as_float(e.y));
    }
    *(reinterpret_cast<float2*>(out + (size_t)node * 64) + lane) = acc;
}

// ---------------- HMMA helpers ------------------------------------------------
__device__ __forceinline__ void ldsm4(unsigned& r0, unsigned& r1, unsigned& r2,
                                      unsigned& r3, unsigned addr) {
    asm volatile("ldmatrix.sync.aligned.m8n8.x4.shared.b16 {%0,%1,%2,%3}, [%4];"
                 : "=r"(r0), "=r"(r1), "=r"(r2), "=r"(r3) : "r"(addr));
}
__device__ __forceinline__ void ldsm4t(unsigned& r0, unsigned& r1, unsigned& r2,
                                       unsigned& r3, unsigned addr) {
    asm volatile("ldmatrix.sync.aligned.m8n8.x4.trans.shared.b16 {%0,%1,%2,%3}, [%4];"
                 : "=r"(r0), "=r"(r1), "=r"(r2), "=r"(r3) : "r"(addr));
}
__device__ __forceinline__ void mma16816(float* d, const unsigned* a, const unsigned* b) {
    asm volatile("mma.sync.aligned.m16n8k16.row.col.f32.f16.f16.f32 "
                 "{%0,%1,%2,%3}, {%4,%5,%6,%7}, {%8,%9}, {%0,%1,%2,%3};"
                 : "+f"(d[0]), "+f"(d[1]), "+f"(d[2]), "+f"(d[3])
                 : "r"(a[0]), "r"(a[1]), "r"(a[2]), "r"(a[3]), "r"(b[0]), "r"(b[1]));
}

// ---------------- HMMA GEMM ---------------------------------------------------
template <bool SPLIT, bool ZFUSE>
__global__ __launch_bounds__(256) void hgemm128(
    const float* __restrict__ A, const __half* __restrict__ Bh,
    const __half* __restrict__ Bl, const float* __restrict__ bias,
    float* __restrict__ C, __half* __restrict__ Ch,
    const float* __restrict__ eps, float* __restrict__ muO,
    float* __restrict__ lvO, float* __restrict__ zO,
    __half* __restrict__ zH, int N, int K)
{
    __shared__ __half sAh[128][24];
    __shared__ __half sBh[16][136];
    __shared__ __half sAl[SPLIT ? 128 : 1][SPLIT ? 24 : 1];
    __shared__ __half sBl[SPLIT ? 16 : 1][SPLIT ? 136 : 1];
    __shared__ __half sLv[ZFUSE ? 128 : 1][ZFUSE ? 64 : 1];

    int tid = threadIdx.x;
    int lane = tid & 31;
    int wid = tid >> 5;
    int wm = (wid & 3) * 32;
    int wn = (wid >> 2) * 64;
    int row0 = blockIdx.y * 128;

    float acc[2][8][4];
#pragma unroll
    for (int i = 0; i < 2; i++)
#pragma unroll
        for (int j = 0; j < 8; j++)
#pragma unroll
            for (int k = 0; k < 4; k++) acc[i][j][k] = 0.f;

    int ar = tid >> 1, ak = (tid & 1) * 8;
    int br = tid & 15, bc = (tid >> 4) * 8;

    unsigned sa_base = (unsigned)__cvta_generic_to_shared(&sAh[0][0]);
    unsigned sb_base = (unsigned)__cvta_generic_to_shared(&sBh[0][0]);
    unsigned sal_base = SPLIT ? (unsigned)__cvta_generic_to_shared(&sAl[0][0]) : 0;
    unsigned sbl_base = SPLIT ? (unsigned)__cvta_generic_to_shared(&sBl[0][0]) : 0;

    const int KSTEPS = K >> 4;
    for (int ks = 0; ks < KSTEPS; ks++) {
        int k0 = ks << 4;
        float va[8] = {0, 0, 0, 0, 0, 0, 0, 0};
        if (row0 + ar < N) {
            const float* ap = A + (size_t)(row0 + ar) * K + k0 + ak;
            float4 f0 = *reinterpret_cast<const float4*>(ap);
            float4 f1 = *reinterpret_cast<const float4*>(ap + 4);
            va[0] = f0.x; va[1] = f0.y; va[2] = f0.z; va[3] = f0.w;
            va[4] = f1.x; va[5] = f1.y; va[6] = f1.z; va[7] = f1.w;
        }
        __half hh[8];
#pragma unroll
        for (int i = 0; i < 8; i++) hh[i] = __float2half_rn(va[i]);
        *reinterpret_cast<uint4*>(&sAh[ar][ak]) = *reinterpret_cast<uint4*>(hh);
        if (SPLIT) {
            __half hl[8];
#pragma unroll
            for (int i = 0; i < 8; i++)
                hl[i] = __float2half_rn(va[i] - __half2float(hh[i]));
            *reinterpret_cast<uint4*>(&sAl[ar][ak]) = *reinterpret_cast<uint4*>(hl);
        }
        *reinterpret_cast<uint4*>(&sBh[br][bc]) =
            *reinterpret_cast<const uint4*>(Bh + (size_t)(k0 + br) * 128 + bc);
        if (SPLIT) {
            *reinterpret_cast<uint4*>(&sBl[br][bc]) =
                *reinterpret_cast<const uint4*>(Bl + (size_t)(k0 + br) * 128 + bc);
        }
        __syncthreads();

        unsigned afh[2][4], afl[2][4];
        int fr = lane & 15;
        int fc = (lane >> 4) * 8;
#pragma unroll
        for (int am = 0; am < 2; am++) {
            unsigned off = (unsigned)(((wm + am * 16 + fr) * 24 + fc) << 1);
            ldsm4(afh[am][0], afh[am][1], afh[am][2], afh[am][3], sa_base + off);
            if (SPLIT)
                ldsm4(afl[am][0], afl[am][1], afl[am][2], afl[am][3], sal_base + off);
        }
        unsigned bfh[8][2], bfl[8][2];
#pragma unroll
        for (int bn = 0; bn < 4; bn++) {
            unsigned off = (unsigned)((fr * 136 + wn + bn * 16 + fc) << 1);
            ldsm4t(bfh[bn * 2][0], bfh[bn * 2][1], bfh[bn * 2 + 1][0], bfh[bn * 2 + 1][1],
                   sb_base + off);
            if (SPLIT)
                ldsm4t(bfl[bn * 2][0], bfl[bn * 2][1], bfl[bn * 2 + 1][0],
                       bfl[bn * 2 + 1][1], sbl_base + off);
        }
#pragma unroll
        for (int am = 0; am < 2; am++)
#pragma unroll
            for (int an = 0; an < 8; an++) {
                mma16816(acc[am][an], afh[am], bfh[an]);
                if (SPLIT) {
                    mma16816(acc[am][an], afh[am], bfl[an]);
                    mma16816(acc[am][an], afl[am], bfh[an]);
                }
            }
        __syncthreads();
    }

    if (!ZFUSE) {
#pragma unroll
        for (int am = 0; am < 2; am++) {
            int rr = row0 + wm + am * 16 + (lane >> 2);
#pragma unroll
            for (int an = 0; an < 8; an++) {
                int cc = wn + an * 8 + (lane & 3) * 2;
                float bv0 = bias ? __ldg(bias + cc) : 0.f;
                float bv1 = bias ? __ldg(bias + cc + 1) : 0.f;
                if (rr < N) {
                    float v0 = acc[am][an][0] + bv0, v1 = acc[am][an][1] + bv1;
                    if (C) *reinterpret_cast<float2*>(C + (size_t)rr * 128 + cc) = make_float2(v0, v1);
                    if (Ch) *reinterpret_cast<__half2*>(Ch + (size_t)rr * 128 + cc) = __floats2half2_rn(v0, v1);
                }
                if (rr + 8 < N) {
                    float v2 = acc[am][an][2] + bv0, v3 = acc[am][an][3] + bv1;
                    if (C) *reinterpret_cast<float2*>(C + (size_t)(rr + 8) * 128 + cc) = make_float2(v2, v3);
                    if (Ch) *reinterpret_cast<__half2*>(Ch + (size_t)(rr + 8) * 128 + cc) = __floats2half2_rn(v2, v3);
                }
            }
        }
    } else {
        if (wn == 64) {
#pragma unroll
            for (int am = 0; am < 2; am++) {
                int r = wm + am * 16 + (lane >> 2);
                int rr = row0 + r;
#pragma unroll
                for (int an = 0; an < 8; an++) {
                    int cl = an * 8 + (lane & 3) * 2;
                    float bv0 = __ldg(bias + 64 + cl);
                    float bv1 = __ldg(bias + 64 + cl + 1);
                    float v0 = acc[am][an][0] + bv0, v1 = acc[am][an][1] + bv1;
                    float v2 = acc[am][an][2] + bv0, v3 = acc[am][an][3] + bv1;
                    *reinterpret_cast<__half2*>(&sLv[r][cl]) = __floats2half2_rn(v0, v1);
                    *reinterpret_cast<__half2*>(&sLv[r + 8][cl]) = __floats2half2_rn(v2, v3);
                    if (rr < N)
                        *reinterpret_cast<float2*>(lvO + (size_t)rr * 64 + cl) = make_float2(v0, v1);
                    if (rr + 8 < N)
                        *reinterpret_cast<float2*>(lvO + (size_t)(rr + 8) * 64 + cl) = make_float2(v2, v3);
                }
            }
        }
        __syncthreads();
        if (wn == 0) {
#pragma unroll
            for (int am = 0; am < 2; am++) {
                int r = wm + am * 16 + (lane >> 2);
#pragma unroll
                for (int an = 0; an < 8; an++) {
                    int cl = an * 8 + (lane & 3) * 2;
                    float bv0 = __ldg(bias + cl);
                    float bv1 = __ldg(bias + cl + 1);
#pragma unroll
                    for (int half = 0; half < 2; half++) {
                        int rr = row0 + r + half * 8;
                        if (rr >= N) continue;
                        float m0 = acc[am][an][half * 2] + bv0;
                        float m1 = acc[am][an][half * 2 + 1] + bv1;
                        float2 lvp = __half22float2(
                            *reinterpret_cast<__half2*>(&sLv[r + half * 8][cl]));
                        float2 ep = *reinterpret_cast<const float2*>(
                            eps + (size_t)rr * 64 + cl);
                        float z0 = ep.x * expf(0.5f * lvp.x) + m0;
                        float z1 = ep.y * expf(0.5f * lvp.y) + m1;
                        *reinterpret_cast<float2*>(muO + (size_t)rr * 64 + cl) = make_float2(m0, m1);
                        *reinterpret_cast<float2*>(zO + (size_t)rr * 64 + cl) = make_float2(z0, z1);
                        *reinterpret_cast<__half2*>(zH + (size_t)rr * 64 + cl) = __floats2half2_rn(z0, z1);
                    }
                }
            }
        }
    }
}

// ---------------- heads: gender (gumbel) + logits_label ----------------------
__global__ __launch_bounds__(256) void heads(
    const float* __restrict__ z, const float* __restrict__ u,
    const float* __restrict__ Wg, const float* __restrict__ bg,
    const float* __restrict__ Wlc, const float* __restrict__ blc,
    float* __restrict__ gender, float* __restrict__ label, int n)
{
    int node = (blockIdx.x * blockDim.x + threadIdx.x) >> 5;
    if (node >= n) return;
    int lane = threadIdx.x & 31;
    float2 a  = *(reinterpret_cast<const float2*>(g_az + (size_t)node * 64) + lane);
    float2 zz = __ldg(reinterpret_cast<const float2*>(z + (size_t)node * 64) + lane);
    int k = lane * 2;
    float p0 = a.x * Wg[k * 2 + 0] + a.y * Wg[(k + 1) * 2 + 0];
    float p1 = a.x * Wg[k * 2 + 1] + a.y * Wg[(k + 1) * 2 + 1];
    float pl = zz.x * Wlc[k] + zz.y * Wlc[k + 1];
#pragma unroll
    for (int off = 16; off; off >>= 1) {
        p0 += __shfl_xor_sync(0xffffffffu, p0, off);
        p1 += __shfl_xor_sync(0xffffffffu, p1, off);
        pl += __shfl_xor_sync(0xffffffffu, pl, off);
    }
    if (lane == 0) {
        float l0 = p0 + bg[0], l1 = p1 + bg[1];
        float u0 = u[(size_t)node * 2], u1 = u[(size_t)node * 2 + 1];
        float gn0 = -logf(-logf(u0 + 1e-20f) + 1e-20f);
        float gn1 = -logf(-logf(u1 + 1e-20f) + 1e-20f);
        float a0 = l0 + gn0, a1 = l1 + gn1;
        float m = fmaxf(a0, a1);
        float e0 = expf(a0 - m), e1 = expf(a1 - m);
        float inv = 1.0f / (e0 + e1);
        float s0 = e0 * inv, s1 = e1 * inv;
        float h0 = (s0 >= s1) ? 1.0f : 0.0f;
        float h1 = 1.0f - h0;
        gender[(size_t)node * 2 + 0] = (h0 - s0) + s0;
        gender[(size_t)node * 2 + 1] = (h1 - s1) + s1;
        label[node] = pl + blc[0];
    }
}

// ---------------- launch -----------------------------------------------------
extern "C" void kernel_launch(void* const* d_in, const int* in_sizes, int n_in,
                              void* d_out, int out_size) {
    const float* x   = (const float*)d_in[0];
    const int*   ei  = (const int*)d_in[1];
    const float* eps = (const float*)d_in[2];
    const float* u   = (const float*)d_in[3];
    const float* W1  = (const float*)d_in[4];
    const float* b1  = (const float*)d_in[5];
    const float* Wmu = (const float*)d_in[6];
    const float* bmu = (const float*)d_in[7];
    const float* Wls = (const float*)d_in[8];
    const float* bls = (const float*)d_in[9];
    const float* Wdx = (const float*)d_in[10];
    const float* bdx = (const float*)d_in[11];
    const float* Wg  = (const float*)d_in[12];
    const float* bg  = (const float*)d_in[13];
    const float* Wlc = (const float*)d_in[14];
    const float* blc = (const float*)d_in[15];

    const int N = in_sizes[0] / 128;
    const int E = in_sizes[1] / 2;
    const int* src = ei;
    const int* dst = ei + E;

    float* out    = (float*)d_out;
    float* recon  = out;                     // [N,128]
    float* gender = out + (size_t)N * 128;   // [N,2]
    float* label  = gender + (size_t)N * 2;  // [N,1]
    float* mu     = label + N;               // [N,64]
    float* lv     = mu + (size_t)N * 64;     // [N,64]
    float* z      = lv + (size_t)N * 64;     // [N,64]

    float *p_acc, *p_az, *p_bpack;
    __half *p_tb, *p_hb, *p_zh, *p_w1h, *p_wdxh, *p_wph, *p_wpl;
    cudaGetSymbolAddress((void**)&p_tb, g_tb);
    cudaGetSymbolAddress((void**)&p_hb, g_hb);
    cudaGetSymbolAddress((void**)&p_zh, g_zh);
    cudaGetSymbolAddress((void**)&p_acc, g_acc);
    cudaGetSymbolAddress((void**)&p_az, g_az);
    cudaGetSymbolAddress((void**)&p_bpack, g_bpack);
    cudaGetSymbolAddress((void**)&p_w1h, g_w1h);
    cudaGetSymbolAddress((void**)&p_wdxh, g_wdxh);
    cudaGetSymbolAddress((void**)&p_wph, g_wph);
    cudaGetSymbolAddress((void**)&p_wpl, g_wpl);

    // persistent side streams / events for graph-parallel branches
    static cudaStream_t s1 = nullptr, s2 = nullptr;
    static cudaEvent_t evRoot = nullptr, evW = nullptr, evAz = nullptr, evH = nullptr;
    if (!s1) {
        cudaStreamCreateWithFlags(&s1, cudaStreamNonBlocking);
        cudaStreamCreateWithFlags(&s2, cudaStreamNonBlocking);
        cudaEventCreateWithFlags(&evRoot, cudaEventDisableTiming);
        cudaEventCreateWithFlags(&evW, cudaEventDisableTiming);
        cudaEventCreateWithFlags(&evAz, cudaEventDisableTiming);
        cudaEventCreateWithFlags(&evH, cudaEventDisableTiming);
    }

    const int T = 256;
    int nodeWarpBlocks = (int)(((size_t)N * 32 + T - 1) / T);
    int nScanBlocks = (N + 1023) / 1024;
    int e4Blocks = ((E + 3) / 4 + T - 1) / T;
    dim3 gg(1, (N + 127) / 128);

    // ---- fork: branch B (weights + t-GEMM) runs parallel to CSR build ----
    cudaEventRecord(evRoot, 0);
    cudaStreamWaitEvent(s1, evRoot, 0);
    cvt_weights<<<(128 * 128 + T - 1) / T, T, 0, s1>>>(W1, Wdx, Wmu, Wls, bmu, bls);
    hgemm128<false, false><<<gg, 256, 0, s1>>>(x, p_w1h, nullptr, nullptr, nullptr, p_tb,
                                               nullptr, nullptr, nullptr, nullptr, nullptr, N, 128);
    cudaEventRecord(evW, s1);

    // ---- main stream: CSR build ----
    zero_cnt<<<(N + T - 1) / T, T>>>(N);
    cnt_count4<<<e4Blocks, T>>>(dst, E);
    scan_blocks<<<nScanBlocks, 1024>>>(N);
    add_bsum2<<<(N + T - 1) / T, T>>>(N, nScanBlocks);
    csr_fill4<<<e4Blocks, T>>>(src, dst, E);

    // ---- join: aggs need both CSR and t-table ----
    cudaStreamWaitEvent(0, evW, 0);

    // h = relu(A @ t + b1); ah = A @ h
    agg128h<<<nodeWarpBlocks, T>>>(p_tb, p_hb, nullptr, b1, 1, N);
    agg128h<<<nodeWarpBlocks, T>>>(p_hb, nullptr, p_acc, nullptr, 0, N);

    // [mu|lv] = ah @ [Wmu|Wls] + b -> fused z epilogue
    hgemm128<true, true><<<gg, 256>>>(p_acc, p_wph, p_wpl, p_bpack, nullptr, nullptr,
                                      eps, mu, lv, z, p_zh, N, 128);

    // az = A @ z
    agg64h<<<nodeWarpBlocks, T>>>(p_zh, p_az, N);

    // ---- fork: heads parallel to recon GEMM ----
    cudaEventRecord(evAz, 0);
    cudaStreamWaitEvent(s2, evAz, 0);
    heads<<<nodeWarpBlocks, T, 0, s2>>>(z, u, Wg, bg, Wlc, blc, gender, label, N);
    cudaEventRecord(evH, s2);

    hgemm128<false, false><<<gg, 256>>>(p_az, p_wdxh, nullptr, bdx, recon, nullptr,
                                        nullptr, nullptr, nullptr, nullptr, nullptr, N, 64);

    // ---- join before return ----
    cudaStreamWaitEvent(0, evH, 0);
}

// round 8
// speedup vs baseline: 1.1568x; 1.1568x over previous
#include <cuda_runtime.h>
#include <cuda_fp16.h>
#include <math.h>

#define NMAX 50048
#define EMAX 1700000
#define NBLK ((NMAX + 1023) / 1024)
#define CPAD 8   // counter padding: 1 int per 32B sector

// ---------------- scratch (device globals) ----------------------------------
__device__ __half g_tb[(size_t)NMAX * 128];  // x@W1 table; reused for hp table
__device__ __half g_hb[(size_t)NMAX * 128];  // hidden after relu (fp16 table)
__device__ __half g_zh[(size_t)NMAX * 64];   // z (fp16 gather table)
__device__ float g_az[(size_t)NMAX * 64];    // aggregated z
__device__ float g_dinv[NMAX];               // deg^-0.5
__device__ int   g_cnt[NMAX * CPAD];         // in-degree (padded, stride CPAD)
__device__ int   g_cur[NMAX * CPAD];         // fill cursors (padded)
__device__ int   g_off[NMAX];                // CSR row offsets (+ sentinel at [n])
__device__ int   g_bsum[NBLK];               // scan block sums
__device__ uint2 g_edge[EMAX];               // CSR (src, weight-bits)
__device__ __half g_w1h[128 * 128];          // W1 fp16
__device__ __half g_wdxh[64 * 128];          // Wdx fp16
__device__ __half g_wph[128 * 128];          // [Wmu|Wls] fp16 hi
__device__ __half g_wpl[128 * 128];          // [Wmu|Wls] fp16 lo (residual)
__device__ float g_bpack[128];               // [bmu | bls]

// ---------------- weight conversion (independent branch) ---------------------
__global__ void cvt_weights(const float* __restrict__ W1, const float* __restrict__ Wdx,
                            const float* __restrict__ Wmu, const float* __restrict__ Wls,
                            const float* __restrict__ bmu, const float* __restrict__ bls)
{
    int i = blockIdx.x * blockDim.x + threadIdx.x;
    if (i < 128 * 128) g_w1h[i] = __float2half_rn(W1[i]);
    if (i < 64 * 128) g_wdxh[i] = __float2half_rn(Wdx[i]);
    if (i < 128 * 128) {
        int row = i >> 7, col = i & 127;
        float v = (col < 64) ? Wmu[row * 64 + col] : Wls[row * 64 + (col - 64)];
        __half h = __float2half_rn(v);
        g_wph[i] = h;
        g_wpl[i] = __float2half_rn(v - __half2float(h));
    }
    if (i < 64) { g_bpack[i] = bmu[i]; g_bpack[64 + i] = bls[i]; }
}

// ---------------- degree / CSR build ----------------------------------------
__global__ void zero_cnt(int n) {
    int i = blockIdx.x * blockDim.x + threadIdx.x;
    int total = n * CPAD;
    if (i * 4 + 4 <= total) {
        *reinterpret_cast<int4*>(g_cnt + i * 4) = make_int4(0, 0, 0, 0);
        *reinterpret_cast<int4*>(g_cur + i * 4) = make_int4(0, 0, 0, 0);
    } else {
        for (int k = i * 4; k < total; k++) { g_cnt[k] = 0; g_cur[k] = 0; }
    }
}
// RED (fire-and-forget) count, 4 edges/thread, sector-padded counters
__global__ void cnt_count4(const int* __restrict__ dst, int e) {
    int base = (blockIdx.x * blockDim.x + threadIdx.x) * 4;
    if (base + 4 <= e) {
        int4 d = *reinterpret_cast<const int4*>(dst + base);
        atomicAdd(&g_cnt[d.x * CPAD], 1);
        atomicAdd(&g_cnt[d.y * CPAD], 1);
        atomicAdd(&g_cnt[d.z * CPAD], 1);
        atomicAdd(&g_cnt[d.w * CPAD], 1);
    } else {
        for (int i = base; i < e; i++) atomicAdd(&g_cnt[dst[i] * CPAD], 1);
    }
}
// block scan + dinv in one pass
__global__ __launch_bounds__(1024) void scan_blocks(int n) {
    __shared__ int sh[1024];
    int tid = threadIdx.x;
    int i = blockIdx.x * 1024 + tid;
    int v = (i < n) ? g_cnt[i * CPAD] : 0;
    if (i < n) g_dinv[i] = rsqrtf(1.0f + (float)v);
    sh[tid] = v;
    __syncthreads();
#pragma unroll
    for (int off = 1; off < 1024; off <<= 1) {
        int t = (tid >= off) ? sh[tid - off] : 0;
        __syncthreads();
        sh[tid] += t;
        __syncthreads();
    }
    if (i < n) g_off[i] = sh[tid] - v;
    if (tid == 1023) g_bsum[blockIdx.x] = sh[1023];
}
// every block redundantly scans the <=64 block sums, then adds to its range
__global__ __launch_bounds__(256) void add_bsum2(int n, int nb, int e) {
    __shared__ int sh[64];
    int tid = threadIdx.x;
    if (tid < 64) sh[tid] = (tid < nb) ? g_bsum[tid] : 0;
    __syncthreads();
#pragma unroll
    for (int off = 1; off < 64; off <<= 1) {
        int t = (tid < 64 && tid >= off) ? sh[tid - off] : 0;
        __syncthreads();
        if (tid < 64) sh[tid] += t;
        __syncthreads();
    }
    int i = blockIdx.x * blockDim.x + tid;
    if (i < n) {
        int b = i >> 10;
        g_off[i] += (b == 0) ? 0 : sh[b - 1];
    }
    if (i == 0) g_off[n] = e;  // sentinel so aggs use off[node+1]
}
// atomic fill (return rank from padded cursor), 4 edges/thread
__global__ void csr_fill4(const int* __restrict__ src, const int* __restrict__ dst, int e) {
    int base = (blockIdx.x * blockDim.x + threadIdx.x) * 4;
    if (base + 4 <= e) {
        int4 s = *reinterpret_cast<const int4*>(src + base);
        int4 d = *reinterpret_cast<const int4*>(dst + base);
        int p0 = g_off[d.x] + atomicAdd(&g_cur[d.x * CPAD], 1);
        int p1 = g_off[d.y] + atomicAdd(&g_cur[d.y * CPAD], 1);
        int p2 = g_off[d.z] + atomicAdd(&g_cur[d.z * CPAD], 1);
        int p3 = g_off[d.w] + atomicAdd(&g_cur[d.w * CPAD], 1);
        g_edge[p0] = make_uint2((unsigned)s.x, __float_as_uint(g_dinv[s.x] * g_dinv[d.x]));
        g_edge[p1] = make_uint2((unsigned)s.y, __float_as_uint(g_dinv[s.y] * g_dinv[d.y]));
        g_edge[p2] = make_uint2((unsigned)s.z, __float_as_uint(g_dinv[s.z] * g_dinv[d.z]));
        g_edge[p3] = make_uint2((unsigned)s.w, __float_as_uint(g_dinv[s.w] * g_dinv[d.w]));
    } else {
        for (int i = base; i < e; i++) {
            int s = src[i], d = dst[i];
            int pos = g_off[d] + atomicAdd(&g_cur[d * CPAD], 1);
            g_edge[pos] = make_uint2((unsigned)s, __float_as_uint(g_dinv[s] * g_dinv[d]));
        }
    }
}

// ---------------- fp16 gather helpers ----------------------------------------
__device__ __forceinline__ void acc_h4(float4& acc, uint2 q, float w) {
    __half2 p0 = *reinterpret_cast<__half2*>(&q.x);
    __half2 p1 = *reinterpret_cast<__half2*>(&q.y);
    float2 f0 = __half22float2(p0);
    float2 f1 = __half22float2(p1);
    acc.x += w * f0.x; acc.y += w * f0.y;
    acc.z += w * f1.x; acc.w += w * f1.y;
}
__device__ __forceinline__ void acc_h2(float2& acc, unsigned q, float w) {
    __half2 p = *reinterpret_cast<__half2*>(&q);
    float2 f = __half22float2(p);
    acc.x += w * f.x; acc.y += w * f.y;
}

// ---------------- agg core: warp per node, 128-wide, fp16 table --------------
__device__ __forceinline__ float4 agg128_core(const uint2* fb, int node, int lane) {
    float di = g_dinv[node];
    float4 acc = make_float4(0.f, 0.f, 0.f, 0.f);
    acc_h4(acc, __ldg(fb + (size_t)node * 32 + lane), di * di);
    int j = g_off[node];
    int jend = g_off[node + 1];
    for (; j + 8 <= jend; j += 8) {
        uint2 e[8], q[8];
#pragma unroll
        for (int k = 0; k < 8; k++) e[k] = g_edge[j + k];
#pragma unroll
        for (int k = 0; k < 8; k++) q[k] = __ldg(fb + (size_t)e[k].x * 32 + lane);
#pragma unroll
        for (int k = 0; k < 8; k++) acc_h4(acc, q[k], __uint_as_float(e[k].y));
    }
    for (; j + 2 <= jend; j += 2) {
        uint2 e0 = g_edge[j], e1 = g_edge[j + 1];
        uint2 q0 = __ldg(fb + (size_t)e0.x * 32 + lane);
        uint2 q1 = __ldg(fb + (size_t)e1.x * 32 + lane);
        acc_h4(acc, q0, __uint_as_float(e0.y));
        acc_h4(acc, q1, __uint_as_float(e1.y));
    }
    for (; j < jend; j++) {
        uint2 e = g_edge[j];
        acc_h4(acc, __ldg(fb + (size_t)e.x * 32 + lane), __uint_as_float(e.y));
    }
    return acc;
}

// h = relu(A @ t + b1) -> fp16 table
__global__ __launch_bounds__(256) void agg_h(
    const __half* __restrict__ feat, __half* __restrict__ outh,
    const float* __restrict__ bias, int n)
{
    int node = (blockIdx.x * blockDim.x + threadIdx.x) >> 5;
    if (node >= n) return;
    int lane = threadIdx.x & 31;
    float4 acc = agg128_core(reinterpret_cast<const uint2*>(feat), node, lane);
    float4 b = __ldg(reinterpret_cast<const float4*>(bias) + lane);
    acc.x = fmaxf(acc.x + b.x, 0.f);
    acc.y = fmaxf(acc.y + b.y, 0.f);
    acc.z = fmaxf(acc.z + b.z, 0.f);
    acc.w = fmaxf(acc.w + b.w, 0.f);
    __half2 h0 = __floats2half2_rn(acc.x, acc.y);
    __half2 h1 = __floats2half2_rn(acc.z, acc.w);
    uint2 q;
    q.x = *reinterpret_cast<unsigned*>(&h0);
    q.y = *reinterpret_cast<unsigned*>(&h1);
    *(reinterpret_cast<uint2*>(outh) + (size_t)node * 32 + lane) = q;
}

// [mu|lv] = A @ hp + bpack; epilogue: z = eps*exp(0.5*lv)+mu
// lanes 0-15 hold mu cols, lanes 16-31 hold lv cols; exchange via shfl
__global__ __launch_bounds__(256) void agg_z(
    const __half* __restrict__ feat, const float* __restrict__ eps,
    float* __restrict__ muO, float* __restrict__ lvO,
    float* __restrict__ zO, __half* __restrict__ zH, int n)
{
    int node = (blockIdx.x * blockDim.x + threadIdx.x) >> 5;
    if (node >= n) return;
    int lane = threadIdx.x & 31;
    float4 acc = agg128_core(reinterpret_cast<const uint2*>(feat), node, lane);
    float4 b = __ldg(reinterpret_cast<const float4*>(g_bpack) + lane);
    acc.x += b.x; acc.y += b.y; acc.z += b.z; acc.w += b.w;

    float4 other;
    other.x = __shfl_xor_sync(0xffffffffu, acc.x, 16);
    other.y = __shfl_xor_sync(0xffffffffu, acc.y, 16);
    other.z = __shfl_xor_sync(0xffffffffu, acc.z, 16);
    other.w = __shfl_xor_sync(0xffffffffu, acc.w, 16);

    if (lane < 16) {
        // acc = mu cols 4*lane.., other = matching lv cols
        float4 ep = __ldg(reinterpret_cast<const float4*>(eps + (size_t)node * 64) + lane);
        float4 zv;
        zv.x = ep.x * expf(0.5f * other.x) + acc.x;
        zv.y = ep.y * expf(0.5f * other.y) + acc.y;
        zv.z = ep.z * expf(0.5f * other.z) + acc.z;
        zv.w = ep.w * expf(0.5f * other.w) + acc.w;
        *(reinterpret_cast<float4*>(muO + (size_t)node * 64) + lane) = acc;
        *(reinterpret_cast<float4*>(zO + (size_t)node * 64) + lane) = zv;
        __half2 h0 = __floats2half2_rn(zv.x, zv.y);
        __half2 h1 = __floats2half2_rn(zv.z, zv.w);
        uint2 q;
        q.x = *reinterpret_cast<unsigned*>(&h0);
        q.y = *reinterpret_cast<unsigned*>(&h1);
        *(reinterpret_cast<uint2*>(zH) + (size_t)node * 16 + lane) = q;
    } else {
        *(reinterpret_cast<float4*>(lvO + (size_t)node * 64) + (lane - 16)) = acc;
    }
}

// ---------------- aggregation: warp per node, 64-wide, fp16 table ------------
__global__ __launch_bounds__(256) void agg64h(
    const __half* __restrict__ feat, float* __restrict__ out, int n)
{
    int node = (blockIdx.x * blockDim.x + threadIdx.x) >> 5;
    if (node >= n) return;
    int lane = threadIdx.x & 31;
    const unsigned* fb = reinterpret_cast<const unsigned*>(feat);

    float di = g_dinv[node];
    float2 acc = make_float2(0.f, 0.f);
    acc_h2(acc, __ldg(fb + (size_t)node * 32 + lane), di * di);

    int j = g_off[node];
    int jend = g_off[node + 1];
    for (; j + 8 <= jend; j += 8) {
        uint2 e[8];
        unsigned q[8];
#pragma unroll
        for (int k = 0; k < 8; k++) e[k] = g_edge[j + k];
#pragma unroll
        for (int k = 0; k < 8; k++) q[k] = __ldg(fb + (size_t)e[k].x * 32 + lane);
#pragma unroll
        for (int k = 0; k < 8; k++) acc_h2(acc, q[k], __uint_as_float(e[k].y));
    }
    for (; j < jend; j++) {
        uint2 e = g_edge[j];
        acc_h2(acc, __ldg(fb + (size_t)e.x * 32 + lane), __uint_as_float(e.y));
    }
    *(reinterpret_cast<float2*>(out + (size_t)node * 64) + lane) = acc;
}

// ---------------- HMMA helpers ------------------------------------------------
__device__ __forceinline__ void ldsm4(unsigned& r0, unsigned& r1, unsigned& r2,
                                      unsigned& r3, unsigned addr) {
    asm volatile("ldmatrix.sync.aligned.m8n8.x4.shared.b16 {%0,%1,%2,%3}, [%4];"
                 : "=r"(r0), "=r"(r1), "=r"(r2), "=r"(r3) : "r"(addr));
}
__device__ __forceinline__ void ldsm4t(unsigned& r0, unsigned& r1, unsigned& r2,
                                       unsigned& r3, unsigned addr) {
    asm volatile("ldmatrix.sync.aligned.m8n8.x4.trans.shared.b16 {%0,%1,%2,%3}, [%4];"
                 : "=r"(r0), "=r"(r1), "=r"(r2), "=r"(r3) : "r"(addr));
}
__device__ __forceinline__ void mma16816(float* d, const unsigned* a, const unsigned* b) {
    asm volatile("mma.sync.aligned.m16n8k16.row.col.f32.f16.f16.f32 "
                 "{%0,%1,%2,%3}, {%4,%5,%6,%7}, {%8,%9}, {%0,%1,%2,%3};"
                 : "+f"(d[0]), "+f"(d[1]), "+f"(d[2]), "+f"(d[3])
                 : "r"(a[0]), "r"(a[1]), "r"(a[2]), "r"(a[3]), "r"(b[0]), "r"(b[1]));
}

// ---------------- HMMA GEMM: A fp32 -> fp16, plain ---------------------------
__global__ __launch_bounds__(256) void hgemm128(
    const float* __restrict__ A, const __half* __restrict__ Bh,
    const float* __restrict__ bias, float* __restrict__ C,
    __half* __restrict__ Ch, int N, int K)
{
    __shared__ __half sAh[128][24];
    __shared__ __half sBh[16][136];

    int tid = threadIdx.x;
    int lane = tid & 31;
    int wid = tid >> 5;
    int wm = (wid & 3) * 32;
    int wn = (wid >> 2) * 64;
    int row0 = blockIdx.y * 128;

    float acc[2][8][4];
#pragma unroll
    for (int i = 0; i < 2; i++)
#pragma unroll
        for (int j = 0; j < 8; j++)
#pragma unroll
            for (int k = 0; k < 4; k++) acc[i][j][k] = 0.f;

    int ar = tid >> 1, ak = (tid & 1) * 8;
    int br = tid & 15, bc = (tid >> 4) * 8;

    unsigned sa_base = (unsigned)__cvta_generic_to_shared(&sAh[0][0]);
    unsigned sb_base = (unsigned)__cvta_generic_to_shared(&sBh[0][0]);

    const int KSTEPS = K >> 4;
    for (int ks = 0; ks < KSTEPS; ks++) {
        int k0 = ks << 4;
        float va[8] = {0, 0, 0, 0, 0, 0, 0, 0};
        if (row0 + ar < N) {
            const float* ap = A + (size_t)(row0 + ar) * K + k0 + ak;
            float4 f0 = *reinterpret_cast<const float4*>(ap);
            float4 f1 = *reinterpret_cast<const float4*>(ap + 4);
            va[0] = f0.x; va[1] = f0.y; va[2] = f0.z; va[3] = f0.w;
            va[4] = f1.x; va[5] = f1.y; va[6] = f1.z; va[7] = f1.w;
        }
        __half hh[8];
#pragma unroll
        for (int i = 0; i < 8; i++) hh[i] = __float2half_rn(va[i]);
        *reinterpret_cast<uint4*>(&sAh[ar][ak]) = *reinterpret_cast<uint4*>(hh);
        *reinterpret_cast<uint4*>(&sBh[br][bc]) =
            *reinterpret_cast<const uint4*>(Bh + (size_t)(k0 + br) * 128 + bc);
        __syncthreads();

        unsigned afh[2][4];
        int fr = lane & 15;
        int fc = (lane >> 4) * 8;
#pragma unroll
        for (int am = 0; am < 2; am++) {
            unsigned off = (unsigned)(((wm + am * 16 + fr) * 24 + fc) << 1);
            ldsm4(afh[am][0], afh[am][1], afh[am][2], afh[am][3], sa_base + off);
        }
        unsigned bfh[8][2];
#pragma unroll
        for (int bn = 0; bn < 4; bn++) {
            unsigned off = (unsigned)((fr * 136 + wn + bn * 16 + fc) << 1);
            ldsm4t(bfh[bn * 2][0], bfh[bn * 2][1], bfh[bn * 2 + 1][0], bfh[bn * 2 + 1][1],
                   sb_base + off);
        }
#pragma unroll
        for (int am = 0; am < 2; am++)
#pragma unroll
            for (int an = 0; an < 8; an++)
                mma16816(acc[am][an], afh[am], bfh[an]);
        __syncthreads();
    }

#pragma unroll
    for (int am = 0; am < 2; am++) {
        int rr = row0 + wm + am * 16 + (lane >> 2);
#pragma unroll
        for (int an = 0; an < 8; an++) {
            int cc = wn + an * 8 + (lane & 3) * 2;
            float bv0 = bias ? __ldg(bias + cc) : 0.f;
            float bv1 = bias ? __ldg(bias + cc + 1) : 0.f;
            if (rr < N) {
                float v0 = acc[am][an][0] + bv0, v1 = acc[am][an][1] + bv1;
                if (C) *reinterpret_cast<float2*>(C + (size_t)rr * 128 + cc) = make_float2(v0, v1);
                if (Ch) *reinterpret_cast<__half2*>(Ch + (size_t)rr * 128 + cc) = __floats2half2_rn(v0, v1);
            }
            if (rr + 8 < N) {
                float v2 = acc[am][an][2] + bv0, v3 = acc[am][an][3] + bv1;
                if (C) *reinterpret_cast<float2*>(C + (size_t)(rr + 8) * 128 + cc) = make_float2(v2, v3);
                if (Ch) *reinterpret_cast<__half2*>(Ch + (size_t)(rr + 8) * 128 + cc) = __floats2half2_rn(v2, v3);
            }
        }
    }
}

// ---------------- HMMA GEMM: A fp16 table @ (Bh + Bl) -> fp16 table ----------
// hp = h @ [Wmu|Wls], B carried hi+lo (near-fp32 weights), A exact fp16.
__global__ __launch_bounds__(256) void hgemm_hh(
    const __half* __restrict__ A, const __half* __restrict__ Bh,
    const __half* __restrict__ Bl, __half* __restrict__ Chp, int N)
{
    const int K = 128;
    __shared__ __half sAh[128][24];
    __shared__ __half sBh[16][136];
    __shared__ __half sBl[16][136];

    int tid = threadIdx.x;
    int lane = tid & 31;
    int wid = tid >> 5;
    int wm = (wid & 3) * 32;
    int wn = (wid >> 2) * 64;
    int row0 = blockIdx.y * 128;

    float acc[2][8][4];
#pragma unroll
    for (int i = 0; i < 2; i++)
#pragma unroll
        for (int j = 0; j < 8; j++)
#pragma unroll
            for (int k = 0; k < 4; k++) acc[i][j][k] = 0.f;

    int ar = tid >> 1, ak = (tid & 1) * 8;
    int br = tid & 15, bc = (tid >> 4) * 8;

    unsigned sa_base = (unsigned)__cvta_generic_to_shared(&sAh[0][0]);
    unsigned sb_base = (unsigned)__cvta_generic_to_shared(&sBh[0][0]);
    unsigned sbl_base = (unsigned)__cvta_generic_to_shared(&sBl[0][0]);

    for (int ks = 0; ks < 8; ks++) {
        int k0 = ks << 4;
        uint4 av = make_uint4(0, 0, 0, 0);
        if (row0 + ar < N)
            av = *reinterpret_cast<const uint4*>(A + (size_t)(row0 + ar) * K + k0 + ak);
        *reinterpret_cast<uint4*>(&sAh[ar][ak]) = av;
        *reinterpret_cast<uint4*>(&sBh[br][bc]) =
            *reinterpret_cast<const uint4*>(Bh + (size_t)(k0 + br) * 128 + bc);
        *reinterpret_cast<uint4*>(&sBl[br][bc]) =
            *reinterpret_cast<const uint4*>(Bl + (size_t)(k0 + br) * 128 + bc);
        __syncthreads();

        unsigned afh[2][4];
        int fr = lane & 15;
        int fc = (lane >> 4) * 8;
#pragma unroll
        for (int am = 0; am < 2; am++) {
            unsigned off = (unsigned)(((wm + am * 16 + fr) * 24 + fc) << 1);
            ldsm4(afh[am][0], afh[am][1], afh[am][2], afh[am][3], sa_base + off);
        }
        unsigned bfh[8][2], bfl[8][2];
#pragma unroll
        for (int bn = 0; bn < 4; bn++) {
            unsigned off = (unsigned)((fr * 136 + wn + bn * 16 + fc) << 1);
            ldsm4t(bfh[bn * 2][0], bfh[bn * 2][1], bfh[bn * 2 + 1][0], bfh[bn * 2 + 1][1],
                   sb_base + off);
            ldsm4t(bfl[bn * 2][0], bfl[bn * 2][1], bfl[bn * 2 + 1][0], bfl[bn * 2 + 1][1],
                   sbl_base + off);
        }
#pragma unroll
        for (int am = 0; am < 2; am++)
#pragma unroll
            for (int an = 0; an < 8; an++) {
                mma16816(acc[am][an], afh[am], bfh[an]);
                mma16816(acc[am][an], afh[am], bfl[an]);
            }
        __syncthreads();
    }

#pragma unroll
    for (int am = 0; am < 2; am++) {
        int rr = row0 + wm + am * 16 + (lane >> 2);
#pragma unroll
        for (int an = 0; an < 8; an++) {
            int cc = wn + an * 8 + (lane & 3) * 2;
            if (rr < N)
                *reinterpret_cast<__half2*>(Chp + (size_t)rr * 128 + cc) =
                    __floats2half2_rn(acc[am][an][0], acc[am][an][1]);
            if (rr + 8 < N)
                *reinterpret_cast<__half2*>(Chp + (size_t)(rr + 8) * 128 + cc) =
                    __floats2half2_rn(acc[am][an][2], acc[am][an][3]);
        }
    }
}

// ---------------- heads: gender (gumbel) + logits_label ----------------------
__global__ __launch_bounds__(256) void heads(
    const float* __restrict__ z, const float* __restrict__ u,
    const float* __restrict__ Wg, const float* __restrict__ bg,
    const float* __restrict__ Wlc, const float* __restrict__ blc,
    float* __restrict__ gender, float* __restrict__ label, int n)
{
    int node = (blockIdx.x * blockDim.x + threadIdx.x) >> 5;
    if (node >= n) return;
    int lane = threadIdx.x & 31;
    float2 a  = *(reinterpret_cast<const float2*>(g_az + (size_t)node * 64) + lane);
    float2 zz = __ldg(reinterpret_cast<const float2*>(z + (size_t)node * 64) + lane);
    int k = lane * 2;
    float p0 = a.x * Wg[k * 2 + 0] + a.y * Wg[(k + 1) * 2 + 0];
    float p1 = a.x * Wg[k * 2 + 1] + a.y * Wg[(k + 1) * 2 + 1];
    float pl = zz.x * Wlc[k] + zz.y * Wlc[k + 1];
#pragma unroll
    for (int off = 16; off; off >>= 1) {
        p0 += __shfl_xor_sync(0xffffffffu, p0, off);
        p1 += __shfl_xor_sync(0xffffffffu, p1, off);
        pl += __shfl_xor_sync(0xffffffffu, pl, off);
    }
    if (lane == 0) {
        float l0 = p0 + bg[0], l1 = p1 + bg[1];
        float u0 = u[(size_t)node * 2], u1 = u[(size_t)node * 2 + 1];
        float gn0 = -logf(-logf(u0 + 1e-20f) + 1e-20f);
        float gn1 = -logf(-logf(u1 + 1e-20f) + 1e-20f);
        float a0 = l0 + gn0, a1 = l1 + gn1;
        float m = fmaxf(a0, a1);
        float e0 = expf(a0 - m), e1 = expf(a1 - m);
        float inv = 1.0f / (e0 + e1);
        float s0 = e0 * inv, s1 = e1 * inv;
        float h0 = (s0 >= s1) ? 1.0f : 0.0f;
        float h1 = 1.0f - h0;
        gender[(size_t)node * 2 + 0] = (h0 - s0) + s0;
        gender[(size_t)node * 2 + 1] = (h1 - s1) + s1;
        label[node] = pl + blc[0];
    }
}

// ---------------- launch -----------------------------------------------------
extern "C" void kernel_launch(void* const* d_in, const int* in_sizes, int n_in,
                              void* d_out, int out_size) {
    const float* x   = (const float*)d_in[0];
    const int*   ei  = (const int*)d_in[1];
    const float* eps = (const float*)d_in[2];
    const float* u   = (const float*)d_in[3];
    const float* W1  = (const float*)d_in[4];
    const float* b1  = (const float*)d_in[5];
    const float* Wmu = (const float*)d_in[6];
    const float* bmu = (const float*)d_in[7];
    const float* Wls = (const float*)d_in[8];
    const float* bls = (const float*)d_in[9];
    const float* Wdx = (const float*)d_in[10];
    const float* bdx = (const float*)d_in[11];
    const float* Wg  = (const float*)d_in[12];
    const float* bg  = (const float*)d_in[13];
    const float* Wlc = (const float*)d_in[14];
    const float* blc = (const float*)d_in[15];

    const int N = in_sizes[0] / 128;
    const int E = in_sizes[1] / 2;
    const int* src = ei;
    const int* dst = ei + E;

    float* out    = (float*)d_out;
    float* recon  = out;                     // [N,128]
    float* gender = out + (size_t)N * 128;   // [N,2]
    float* label  = gender + (size_t)N * 2;  // [N,1]
    float* mu     = label + N;               // [N,64]
    float* lv     = mu + (size_t)N * 64;     // [N,64]
    float* z      = lv + (size_t)N * 64;     // [N,64]

    float *p_az;
    __half *p_tb, *p_hb, *p_zh, *p_w1h, *p_wdxh, *p_wph, *p_wpl;
    cudaGetSymbolAddress((void**)&p_tb, g_tb);
    cudaGetSymbolAddress((void**)&p_hb, g_hb);
    cudaGetSymbolAddress((void**)&p_zh, g_zh);
    cudaGetSymbolAddress((void**)&p_az, g_az);
    cudaGetSymbolAddress((void**)&p_w1h, g_w1h);
    cudaGetSymbolAddress((void**)&p_wdxh, g_wdxh);
    cudaGetSymbolAddress((void**)&p_wph, g_wph);
    cudaGetSymbolAddress((void**)&p_wpl, g_wpl);

    // persistent side streams / events for graph-parallel branches
    static cudaStream_t s1 = nullptr, s2 = nullptr;
    static cudaEvent_t evRoot = nullptr, evW = nullptr, evAz = nullptr, evH = nullptr;
    if (!s1) {
        cudaStreamCreateWithFlags(&s1, cudaStreamNonBlocking);
        cudaStreamCreateWithFlags(&s2, cudaStreamNonBlocking);
        cudaEventCreateWithFlags(&evRoot, cudaEventDisableTiming);
        cudaEventCreateWithFlags(&evW, cudaEventDisableTiming);
        cudaEventCreateWithFlags(&evAz, cudaEventDisableTiming);
        cudaEventCreateWithFlags(&evH, cudaEventDisableTiming);
    }

    const int T = 256;
    int nodeWarpBlocks = (int)(((size_t)N * 32 + T - 1) / T);
    int nScanBlocks = (N + 1023) / 1024;
    int e4Blocks = ((E + 3) / 4 + T - 1) / T;
    int zeroBlocks = ((N * CPAD + 3) / 4 + T - 1) / T;
    dim3 gg(1, (N + 127) / 128);

    // ---- fork: branch B (weights + t-GEMM) runs parallel to CSR build ----
    cudaEventRecord(evRoot, 0);
    cudaStreamWaitEvent(s1, evRoot, 0);
    cvt_weights<<<(128 * 128 + T - 1) / T, T, 0, s1>>>(W1, Wdx, Wmu, Wls, bmu, bls);
    hgemm128<<<gg, 256, 0, s1>>>(x, p_w1h, nullptr, nullptr, p_tb, N, 128);
    cudaEventRecord(evW, s1);

    // ---- main stream: CSR build ----
    zero_cnt<<<zeroBlocks, T>>>(N);
    cnt_count4<<<e4Blocks, T>>>(dst, E);
    scan_blocks<<<nScanBlocks, 1024>>>(N);
    add_bsum2<<<(N + T - 1) / T, T>>>(N, nScanBlocks, E);
    csr_fill4<<<e4Blocks, T>>>(src, dst, E);

    // ---- join: aggs need both CSR and t-table ----
    cudaStreamWaitEvent(0, evW, 0);

    // h = relu(A @ t + b1)
    agg_h<<<nodeWarpBlocks, T>>>(p_tb, p_hb, b1, N);

    // hp = h @ [Wmu|Wls]  (fp16 table, reuses g_tb)
    hgemm_hh<<<gg, 256>>>(p_hb, p_wph, p_wpl, p_tb, N);

    // [mu|lv] = A @ hp + b; z = eps*exp(0.5*lv)+mu (fused epilogue)
    agg_z<<<nodeWarpBlocks, T>>>(p_tb, eps, mu, lv, z, p_zh, N);

    // az = A @ z
    agg64h<<<nodeWarpBlocks, T>>>(p_zh, p_az, N);

    // ---- fork: heads parallel to recon GEMM ----
    cudaEventRecord(evAz, 0);
    cudaStreamWaitEvent(s2, evAz, 0);
    heads<<<nodeWarpBlocks, T, 0, s2>>>(z, u, Wg, bg, Wlc, blc, gender, label, N);
    cudaEventRecord(evH, s2);

    hgemm128<<<gg, 256>>>(p_az, p_wdxh, bdx, recon, nullptr, N, 64);

    // ---- join before return ----
    cudaStreamWaitEvent(0, evH, 0);
}